// round 8
// baseline (speedup 1.0000x reference)
#include <cuda_runtime.h>
#include <cuda_fp16.h>
#include <cstdint>

// Problem constants
#define BT    8192
#define KCB   8192
#define DDIM  128
#define TLEN  1024
#define CCH   256
#define NQ    2097152
#define NIDX  16384

// ---------------------------------------------------------------------------
// Scratch (device globals; no allocation allowed)
// ---------------------------------------------------------------------------
__device__ __align__(16) unsigned g_Ahat[16384 * 128];  // f16x2 [xh(64)|xl(64)] per (n,bt)
__device__ __align__(16) unsigned g_Bhat[16384 * 64];   // f16x2 [ch(64)] per (n,k)
__device__ float  g_c2[2 * KCB];
__device__ float  g_x2[2 * BT];
__device__ int    g_clmax_bits[2];                      // max_k ||cl_k||^2 (float bits)
__device__ float  g_v1[2 * BT], g_v2[2 * BT], g_v3[2 * BT];
__device__ int    g_k1[2 * BT], g_k2[2 * BT];
__device__ int    g_idx[2 * BT];
__device__ int    g_flagq[2 * BT];
__device__ int    g_nflag;
__device__ double g_sse;

// ---------------------------------------------------------------------------
// PTX helpers (compute_103-legal only: ldmatrix / mma.sync / cp.async)
// ---------------------------------------------------------------------------
__device__ __forceinline__ uint32_t smem_u32(const void* p) {
    uint32_t a;
    asm("{ .reg .u64 t; cvta.to.shared.u64 t, %1; cvt.u32.u64 %0, t; }"
        : "=r"(a) : "l"(p));
    return a;
}
__device__ __forceinline__ void ldsm4(uint32_t& r0, uint32_t& r1,
                                      uint32_t& r2, uint32_t& r3, uint32_t a) {
    asm volatile("ldmatrix.sync.aligned.m8n8.x4.shared.b16 {%0,%1,%2,%3}, [%4];"
                 : "=r"(r0), "=r"(r1), "=r"(r2), "=r"(r3) : "r"(a));
}
__device__ __forceinline__ void mma_f16(float* d, uint32_t a0, uint32_t a1,
                                        uint32_t a2, uint32_t a3,
                                        uint32_t b0, uint32_t b1) {
    asm volatile(
        "mma.sync.aligned.m16n8k16.row.col.f32.f16.f16.f32 "
        "{%0,%1,%2,%3}, {%4,%5,%6,%7}, {%8,%9}, {%0,%1,%2,%3};"
        : "+f"(d[0]), "+f"(d[1]), "+f"(d[2]), "+f"(d[3])
        : "r"(a0), "r"(a1), "r"(a2), "r"(a3), "r"(b0), "r"(b1));
}
__device__ __forceinline__ void cp_async16(uint32_t dst, const void* src) {
    asm volatile("cp.async.cg.shared.global [%0], [%1], 16;"
                 :: "r"(dst), "l"(src) : "memory");
}
#define CP_COMMIT() asm volatile("cp.async.commit_group;" ::: "memory")
#define CP_WAIT0()  asm volatile("cp.async.wait_group 0;" ::: "memory")
#define CP_WAIT1()  asm volatile("cp.async.wait_group 1;" ::: "memory")

// fp16 packers
__device__ __forceinline__ unsigned pack_h2(__half a, __half b) {
    unsigned r;
    unsigned short ua = __half_as_ushort(a), ub = __half_as_ushort(b);
    r = (unsigned)ua | ((unsigned)ub << 16);
    return r;
}

// ---------------------------------------------------------------------------
__global__ void init_kernel() {
    if (blockIdx.x == 0 && threadIdx.x == 0) {
        g_sse = 0.0; g_nflag = 0;
        g_clmax_bits[0] = 0; g_clmax_bits[1] = 0;
    }
}

// splitcb: one warp per codeword row. Emits Bhat (f16x2 ch), g_c2, and
// atomicMax of ||cl||^2 per codebook (exact certificate ingredient).
__global__ void splitcb_kernel(const float* __restrict__ cb) {
    int row  = blockIdx.x * 8 + (threadIdx.x >> 5);
    int lane = threadIdx.x & 31;
    const float4 v = *reinterpret_cast<const float4*>(
        cb + (size_t)row * DDIM + lane * 4);
    float c2 = v.x * v.x + v.y * v.y + v.z * v.z + v.w * v.w;
    __half h0 = __float2half_rn(v.x), h1 = __float2half_rn(v.y);
    __half h2 = __float2half_rn(v.z), h3 = __float2half_rn(v.w);
    float r0 = v.x - __half2float(h0), r1 = v.y - __half2float(h1);
    float r2 = v.z - __half2float(h2), r3 = v.w - __half2float(h3);
    float cl2 = r0 * r0 + r1 * r1 + r2 * r2 + r3 * r3;
    g_Bhat[(size_t)row * 64 + 2 * lane]     = pack_h2(h0, h1);
    g_Bhat[(size_t)row * 64 + 2 * lane + 1] = pack_h2(h2, h3);
    #pragma unroll
    for (int o = 16; o; o >>= 1) {
        c2  += __shfl_down_sync(0xFFFFFFFFu, c2, o);
        cl2 += __shfl_down_sync(0xFFFFFFFFu, cl2, o);
    }
    if (lane == 0) {
        g_c2[row] = c2;
        atomicMax(&g_clmax_bits[row >> 13], __float_as_int(cl2));
    }
}

// x2[n*BT+bt] = sum_d x^2
__global__ void x2_kernel(const float* __restrict__ x) {
    int bi = blockIdx.x;
    int n  = bi >> 8;
    int b  = (bi >> 5) & 7;
    int t0 = (bi & 31) * 32;
    int tt = threadIdx.x & 31;
    int g  = threadIdx.x >> 5;
    const float* xp = x + ((size_t)b * CCH + (size_t)n * DDIM) * TLEN + t0 + tt;
    float s = 0.f;
    #pragma unroll
    for (int j = 0; j < 16; ++j) {
        float v = xp[(size_t)(g * 16 + j) * TLEN];
        s += v * v;
    }
    __shared__ float sm[8][33];
    sm[g][tt] = s;
    __syncthreads();
    if (threadIdx.x < 32) {
        float tot = 0.f;
        #pragma unroll
        for (int j = 0; j < 8; ++j) tot += sm[j][threadIdx.x];
        g_x2[n * BT + b * TLEN + t0 + threadIdx.x] = tot;
    }
}

// split_x: Ahat[(n,bt)][128 u32] = f16x2 [xh(64) | xl(64)]
// grid 512 = (n:2, b:8, tchunk:32 of 32 t's), block 256.
__global__ void split_x_kernel(const float* __restrict__ x) {
    __shared__ float xs[128 * 33];
    int bi = blockIdx.x;
    int n  = bi >> 8;
    int b  = (bi >> 5) & 7;
    int tc = bi & 31;
    int tid = threadIdx.x;
    int tt  = tid & 31;
    int dg  = tid >> 5;
    const float* xp = x + ((size_t)b * CCH + (size_t)n * DDIM) * TLEN + tc * 32 + tt;
    #pragma unroll
    for (int j = 0; j < 16; ++j) {
        int d = dg * 16 + j;
        xs[d * 33 + tt] = xp[(size_t)d * TLEN];
    }
    __syncthreads();
    // 32 t x 128 words = 4096 words; 16 per thread; coalesced along w
    #pragma unroll
    for (int it = 0; it < 16; ++it) {
        int lin = it * 256 + tid;
        int r   = lin >> 7;
        int w   = lin & 127;
        int bt  = b * TLEN + tc * 32 + r;
        float a, bb;
        if (w < 64) {           // hi pair of dims (2w, 2w+1)
            a  = xs[(2 * w) * 33 + r];
            bb = xs[(2 * w + 1) * 33 + r];
            __half ha = __float2half_rn(a), hb = __float2half_rn(bb);
            g_Ahat[(size_t)(n * BT + bt) * 128 + w] = pack_h2(ha, hb);
        } else {                // lo pair
            int d0 = 2 * (w - 64);
            a  = xs[d0 * 33 + r];
            bb = xs[(d0 + 1) * 33 + r];
            __half ha = __float2half_rn(a), hb = __float2half_rn(bb);
            __half la = __float2half_rn(a - __half2float(ha));
            __half lb = __float2half_rn(bb - __half2float(hb));
            g_Ahat[(size_t)(n * BT + bt) * 128 + w] = pack_h2(la, lb);
        }
    }
}

// ---------------------------------------------------------------------------
// vq_mma: one CTA per (cb n, 128-query tile). 512 threads, 16 warps (8m x 2n).
// A = [xh|xl] 128q x 256 f16 in smem; B = ch tiles (64 cw x 128 f16)
// double-buffered via cp.async. Warp tile 16q x 32cw. Effective K = 256
// (hi and lo A both multiply the SAME B fragments -> B ldsm/traffic halved).
// ---------------------------------------------------------------------------
#define ASTRIDE 528
#define BSTRIDE 272
#define SM_A    0
#define SM_B0   67584
#define SM_B1   84992
#define SM_MV   102400
#define SM_MK   114688
#define SM_TOT  126976

__global__ void __launch_bounds__(512, 1)
vq_mma_kernel() {
    extern __shared__ char smraw[];
    const uint32_t sb = smem_u32(smraw);
    const int tid  = threadIdx.x;
    const int wid  = tid >> 5;
    const int lane = tid & 31;
    const int gq   = lane >> 2;
    const int tq   = lane & 3;
    const int mw   = wid >> 1;          // 0-7 (16q each)
    const int nw   = wid & 1;           // 0-1 (32cw each)
    const int n    = blockIdx.x >> 6;
    const int qbase = (blockIdx.x & 63) * 128;

    const char* bsrc = (const char*)g_Bhat + (size_t)n * KCB * 256;

    // ---- prologue: group0 = A tile + B tile0 ; group1 = B tile1 ----
    {
        const char* asrc = (const char*)g_Ahat + (size_t)(n * BT + qbase) * 512;
        #pragma unroll
        for (int it = 0; it < 8; ++it) {
            int c   = it * 512 + tid;
            int row = c >> 5, col = c & 31;
            cp_async16(sb + SM_A + row * ASTRIDE + col * 16,
                       asrc + (size_t)row * 512 + col * 16);
        }
        #pragma unroll
        for (int it = 0; it < 2; ++it) {
            int c   = it * 512 + tid;
            int row = c >> 4, col = c & 15;
            cp_async16(sb + SM_B0 + row * BSTRIDE + col * 16,
                       bsrc + (size_t)row * 256 + col * 16);
        }
        CP_COMMIT();
        #pragma unroll
        for (int it = 0; it < 2; ++it) {
            int c   = it * 512 + tid;
            int row = c >> 4, col = c & 15;
            cp_async16(sb + SM_B1 + row * BSTRIDE + col * 16,
                       bsrc + (size_t)(64 + row) * 256 + col * 16);
        }
        CP_COMMIT();
    }
    CP_WAIT1();
    __syncthreads();

    const uint32_t lmo = (uint32_t)(lane >> 4) * 16;
    const uint32_t aHi = sb + SM_A +
        (uint32_t)(mw * 16 + (lane & 15)) * ASTRIDE + lmo;
    const uint32_t bAddrP[2] = {
        sb + SM_B0 + (uint32_t)(nw * 32 + (lane & 15)) * BSTRIDE + lmo,
        sb + SM_B1 + (uint32_t)(nw * 32 + (lane & 15)) * BSTRIDE + lmo };

    float v1[2], v2[2], v3[2];
    int   k1[2], k2[2];
    #pragma unroll
    for (int i = 0; i < 2; ++i) {
        v1[i] = v2[i] = v3[i] = 3.4e38f;
        k1[i] = k2[i] = 0;
    }

    for (int iter = 0; iter < 128; ++iter) {
        float acc[4][4];
        #pragma unroll
        for (int nt = 0; nt < 4; ++nt)
            #pragma unroll
            for (int j = 0; j < 4; ++j) acc[nt][j] = 0.f;

        const uint32_t bA = bAddrP[iter & 1];
        #pragma unroll
        for (int ks = 0; ks < 8; ++ks) {
            uint32_t h0, h1, h2, h3, l0, l1, l2, l3;
            uint32_t b0x, b0y, b1x, b1y, b0z, b0w, b1z, b1w;
            ldsm4(h0, h1, h2, h3, aHi + ks * 32);          // xh frag
            ldsm4(l0, l1, l2, l3, aHi + 256 + ks * 32);    // xl frag
            ldsm4(b0x, b0y, b1x, b1y, bA + ks * 32);       // cw 0-15
            ldsm4(b0z, b0w, b1z, b1w, bA + 16 * BSTRIDE + ks * 32); // cw 16-31
            mma_f16(acc[0], h0, h1, h2, h3, b0x, b1x);
            mma_f16(acc[1], h0, h1, h2, h3, b0y, b1y);
            mma_f16(acc[2], h0, h1, h2, h3, b0z, b1z);
            mma_f16(acc[3], h0, h1, h2, h3, b0w, b1w);
            mma_f16(acc[0], l0, l1, l2, l3, b0x, b1x);
            mma_f16(acc[1], l0, l1, l2, l3, b0y, b1y);
            mma_f16(acc[2], l0, l1, l2, l3, b0z, b1z);
            mma_f16(acc[3], l0, l1, l2, l3, b0w, b1w);
        }

        // ---- epilogue: s = c2[k] - 2*xc, per-row top-3 ----
        const int kbw = iter * 64 + nw * 32;
        #pragma unroll
        for (int nt = 0; nt < 4; ++nt) {
            const int kg = kbw + nt * 8 + tq * 2;
            const float2 c2p = __ldg(reinterpret_cast<const float2*>(
                g_c2 + n * KCB + kg));
            #pragma unroll
            for (int r = 0; r < 2; ++r) {
                float s0 = fmaf(acc[nt][r * 2 + 0], -2.0f, c2p.x);
                float s1 = fmaf(acc[nt][r * 2 + 1], -2.0f, c2p.y);
                if (s0 < v3[r]) {
                    if (s0 < v2[r]) {
                        v3[r] = v2[r];
                        if (s0 < v1[r]) { v2[r] = v1[r]; k2[r] = k1[r];
                                          v1[r] = s0;    k1[r] = kg; }
                        else            { v2[r] = s0;    k2[r] = kg; }
                    } else v3[r] = s0;
                }
                if (s1 < v3[r]) {
                    if (s1 < v2[r]) {
                        v3[r] = v2[r];
                        if (s1 < v1[r]) { v2[r] = v1[r]; k2[r] = k1[r];
                                          v1[r] = s1;    k1[r] = kg + 1; }
                        else            { v2[r] = s1;    k2[r] = kg + 1; }
                    } else v3[r] = s1;
                }
            }
        }

        __syncthreads();    // all warps done reading buf[iter&1]

        if (iter + 2 < 128) {
            const char* src = bsrc + (size_t)(iter + 2) * 64 * 256;
            uint32_t dstb = sb + ((iter & 1) ? SM_B1 : SM_B0);
            #pragma unroll
            for (int it = 0; it < 2; ++it) {
                int c   = it * 512 + tid;
                int row = c >> 4, col = c & 15;
                cp_async16(dstb + row * BSTRIDE + col * 16,
                           src + (size_t)row * 256 + col * 16);
            }
            CP_COMMIT();
            CP_WAIT1();     // tile iter+1 ready; iter+2 in flight
        } else {
            CP_WAIT0();
        }
        __syncthreads();
    }

    // ---- merge per-thread top-3 lists (8 lists x 3 per query) ----
    float* MV = (float*)(smraw + SM_MV);
    int*   MK = (int*)(smraw + SM_MK);
    #pragma unroll
    for (int r = 0; r < 2; ++r) {
        const int ql = mw * 16 + r * 8 + gq;
        const int s0 = ql * 24 + (nw * 4 + tq) * 3;
        MV[s0 + 0] = v1[r]; MK[s0 + 0] = k1[r];
        MV[s0 + 1] = v2[r]; MK[s0 + 1] = k2[r];
        MV[s0 + 2] = v3[r]; MK[s0 + 2] = 0;
    }
    __syncthreads();
    if (tid < 128) {
        float b1 = 3.4e38f, b2 = 3.4e38f, b3 = 3.4e38f;
        int   i1 = 1 << 30, i2 = 1 << 30;
        #pragma unroll 4
        for (int j = 0; j < 24; ++j) {
            float v = MV[tid * 24 + j];
            int   k = MK[tid * 24 + j];
            if (v < b1 || (v == b1 && k < i1)) {
                b3 = b2; b2 = b1; i2 = i1; b1 = v; i1 = k;
            } else if (v < b2 || (v == b2 && k < i2)) {
                b3 = b2; b2 = v; i2 = k;
            } else if (v < b3) b3 = v;
        }
        const int q = n * BT + qbase + tid;
        const float x2v = g_x2[q];
        g_v1[q] = x2v + b1; g_v2[q] = x2v + b2; g_v3[q] = x2v + b3;
        g_k1[q] = i1;       g_k2[q] = i2;
    }
}

// ---------------------------------------------------------------------------
// exact JAX-order d2 (identical arithmetic to the passing rounds 1-3)
// ---------------------------------------------------------------------------
__device__ __forceinline__ float exact_d2(const float* __restrict__ x,
                                          const float* __restrict__ cb,
                                          int n, int b, int t, int bt, int k) {
    const float* xp = x + ((size_t)b * CCH + (size_t)n * DDIM) * TLEN + t;
    const float* cp = cb + ((size_t)n * KCB + (size_t)k) * DDIM;
    float xc = 0.f;
    #pragma unroll 8
    for (int d = 0; d < DDIM; ++d) xc = fmaf(xp[(size_t)d * TLEN], cp[d], xc);
    return __fadd_rn(__fsub_rn(g_x2[n * BT + bt], __fmul_rn(2.0f, xc)),
                     g_c2[n * KCB + k]);
}

// ---------------------------------------------------------------------------
// finalize: computed rigorous margin; certify k1 / rescore top-2 / flag
// ---------------------------------------------------------------------------
__global__ void finalize_kernel(const float* __restrict__ x,
                                const float* __restrict__ cb,
                                float* __restrict__ out) {
    int q = blockIdx.x * 256 + threadIdx.x;
    int n = q >> 13, bt = q & 8191, b = bt >> 10, t = bt & 1023;
    float v1 = g_v1[q], v2 = g_v2[q], v3 = g_v3[q];
    int   k1 = g_k1[q], k2 = g_k2[q];
    // MARGIN = 2*eps; eps = 2*||x||*max||cl|| + const (f32-accum + combine)
    float cl2m   = __int_as_float(g_clmax_bits[n]);
    float margin = 4.0f * sqrtf(g_x2[q]) * sqrtf(cl2m) + 1e-3f;
    if (v3 - v1 <= margin) {
        int pos = atomicAdd(&g_nflag, 1);
        g_flagq[pos] = q;
        return;
    }
    int kf = k1;
    if (v2 - v1 <= margin) {
        float da = exact_d2(x, cb, n, b, t, bt, k1);
        float db = exact_d2(x, cb, n, b, t, bt, k2);
        if (db < da || (db == da && k2 < k1)) kf = k2;
    }
    g_idx[q] = kf;
    out[NQ + ((size_t)b * 2 + n) * TLEN + t] = (float)kf;
}

// ---------------------------------------------------------------------------
// fallback: exact full scan for flagged queries
// ---------------------------------------------------------------------------
__global__ void fallback_kernel(const float* __restrict__ x,
                                const float* __restrict__ cb,
                                float* __restrict__ out) {
    __shared__ float sv[256];
    __shared__ int   sk[256];
    int nf = g_nflag;
    for (int i = blockIdx.x; i < nf; i += 32) {
        int q = g_flagq[i];
        int n = q >> 13, bt = q & 8191, b = bt >> 10, t = bt & 1023;
        float bv = 3.4e38f;
        int   bk = 1 << 30;
        for (int j = 0; j < 32; ++j) {
            int k = threadIdx.x + j * 256;
            float d2 = exact_d2(x, cb, n, b, t, bt, k);
            if (d2 < bv || (d2 == bv && k < bk)) { bv = d2; bk = k; }
        }
        sv[threadIdx.x] = bv;
        sk[threadIdx.x] = bk;
        __syncthreads();
        for (int o = 128; o; o >>= 1) {
            if (threadIdx.x < o) {
                float ov = sv[threadIdx.x + o];
                int   ok = sk[threadIdx.x + o];
                if (ov < sv[threadIdx.x] ||
                    (ov == sv[threadIdx.x] && ok < sk[threadIdx.x])) {
                    sv[threadIdx.x] = ov; sk[threadIdx.x] = ok;
                }
            }
            __syncthreads();
        }
        if (threadIdx.x == 0) {
            g_idx[q] = sk[0];
            out[NQ + ((size_t)b * 2 + n) * TLEN + t] = (float)sk[0];
        }
        __syncthreads();
    }
}

// ---------------------------------------------------------------------------
// gather quantized output + commit-loss SSE
// ---------------------------------------------------------------------------
__global__ void gather_kernel(const float* __restrict__ x,
                              const float* __restrict__ cb,
                              float* __restrict__ out) {
    int bi = blockIdx.x;
    int n  = bi >> 13;
    int bt = bi & 8191;
    int b  = bt >> 10;
    int t  = bt & 1023;
    int k  = g_idx[n * BT + bt];
    int i  = threadIdx.x;

    float q = cb[(size_t)n * KCB * DDIM + (size_t)k * DDIM + i];
    size_t oidx = ((size_t)b * CCH + (size_t)n * DDIM + i) * TLEN + t;
    out[oidx] = q;

    float d = x[oidx] - q;
    float s = d * d;
    #pragma unroll
    for (int o = 16; o; o >>= 1) s += __shfl_down_sync(0xFFFFFFFFu, s, o);
    __shared__ float sm4[4];
    if ((i & 31) == 0) sm4[i >> 5] = s;
    __syncthreads();
    if (i == 0)
        atomicAdd(&g_sse, (double)(sm4[0] + sm4[1] + sm4[2] + sm4[3]));
}

__global__ void fin_kernel(float* __restrict__ out) {
    out[NQ + NIDX] = (float)(0.25 * g_sse / (double)((long long)BT * DDIM));
}

// ---------------------------------------------------------------------------
extern "C" void kernel_launch(void* const* d_in, const int* in_sizes, int n_in,
                              void* d_out, int out_size) {
    const float* x  = (const float*)d_in[0];
    const float* cb = (const float*)d_in[1];
    float* out = (float*)d_out;

    cudaFuncSetAttribute(vq_mma_kernel,
                         cudaFuncAttributeMaxDynamicSharedMemorySize, SM_TOT);

    init_kernel<<<1, 32>>>();
    splitcb_kernel<<<2048, 256>>>(cb);
    x2_kernel<<<512, 256>>>(x);
    split_x_kernel<<<512, 256>>>(x);
    vq_mma_kernel<<<128, 512, SM_TOT>>>();
    finalize_kernel<<<64, 256>>>(x, cb, out);
    fallback_kernel<<<32, 256>>>(x, cb, out);
    gather_kernel<<<16384, 128>>>(x, cb, out);
    fin_kernel<<<1, 1>>>(out);
}

// round 9
// speedup vs baseline: 2.5564x; 2.5564x over previous
#include <cuda_runtime.h>
#include <cuda_fp16.h>
#include <cstdint>

// Problem constants
#define BT    8192
#define KCB   8192
#define DDIM  128
#define TLEN  1024
#define CCH   256
#define NQ    2097152
#define NIDX  16384

// ---------------------------------------------------------------------------
// Scratch (device globals; no allocation allowed)
// ---------------------------------------------------------------------------
__device__ __align__(16) unsigned g_Ahat[16384 * 128];  // f16x2 [xh(64)|xl(64)] per (n,bt)
__device__ __align__(16) unsigned g_Bhat[16384 * 64];   // f16x2 [ch(64)] per (n,k)
__device__ float  g_c2[2 * KCB];
__device__ float  g_x2[2 * BT];
__device__ int    g_clmax_bits[2];      // max_k ||cl_k||^2 (float bits, >=0)
__device__ int    g_candk[2 * BT * 8];  // candidate codewords per query
__device__ int    g_candn[2 * BT];      // count, or -1 => fallback
__device__ int    g_idx[2 * BT];
__device__ int    g_flagq[2 * BT];
__device__ int    g_nflag;
__device__ double g_sse;

// ---------------------------------------------------------------------------
// PTX helpers (compute_103-legal only: ldmatrix / mma.sync / cp.async)
// ---------------------------------------------------------------------------
__device__ __forceinline__ uint32_t smem_u32(const void* p) {
    uint32_t a;
    asm("{ .reg .u64 t; cvta.to.shared.u64 t, %1; cvt.u32.u64 %0, t; }"
        : "=r"(a) : "l"(p));
    return a;
}
__device__ __forceinline__ void ldsm4(uint32_t& r0, uint32_t& r1,
                                      uint32_t& r2, uint32_t& r3, uint32_t a) {
    asm volatile("ldmatrix.sync.aligned.m8n8.x4.shared.b16 {%0,%1,%2,%3}, [%4];"
                 : "=r"(r0), "=r"(r1), "=r"(r2), "=r"(r3) : "r"(a));
}
__device__ __forceinline__ void mma_f16(float* d, uint32_t a0, uint32_t a1,
                                        uint32_t a2, uint32_t a3,
                                        uint32_t b0, uint32_t b1) {
    asm volatile(
        "mma.sync.aligned.m16n8k16.row.col.f32.f16.f16.f32 "
        "{%0,%1,%2,%3}, {%4,%5,%6,%7}, {%8,%9}, {%0,%1,%2,%3};"
        : "+f"(d[0]), "+f"(d[1]), "+f"(d[2]), "+f"(d[3])
        : "r"(a0), "r"(a1), "r"(a2), "r"(a3), "r"(b0), "r"(b1));
}
__device__ __forceinline__ void cp_async16(uint32_t dst, const void* src) {
    asm volatile("cp.async.cg.shared.global [%0], [%1], 16;"
                 :: "r"(dst), "l"(src) : "memory");
}
#define CP_COMMIT() asm volatile("cp.async.commit_group;" ::: "memory")
#define CP_WAIT0()  asm volatile("cp.async.wait_group 0;" ::: "memory")
#define CP_WAIT1()  asm volatile("cp.async.wait_group 1;" ::: "memory")

__device__ __forceinline__ unsigned pack_h2(__half a, __half b) {
    unsigned short ua = __half_as_ushort(a), ub = __half_as_ushort(b);
    return (unsigned)ua | ((unsigned)ub << 16);
}

// ---------------------------------------------------------------------------
__global__ void init_kernel() {
    if (blockIdx.x == 0 && threadIdx.x == 0) {
        g_sse = 0.0; g_nflag = 0;
        g_clmax_bits[0] = 0; g_clmax_bits[1] = 0;
    }
}

// splitcb: one warp per codeword row. Emits Bhat (f16x2 ch), g_c2, and
// atomicMax of ||cl||^2 per codebook (certificate ingredient).
__global__ void splitcb_kernel(const float* __restrict__ cb) {
    int row  = blockIdx.x * 8 + (threadIdx.x >> 5);
    int lane = threadIdx.x & 31;
    const float4 v = *reinterpret_cast<const float4*>(
        cb + (size_t)row * DDIM + lane * 4);
    float c2 = v.x * v.x + v.y * v.y + v.z * v.z + v.w * v.w;
    __half h0 = __float2half_rn(v.x), h1 = __float2half_rn(v.y);
    __half h2 = __float2half_rn(v.z), h3 = __float2half_rn(v.w);
    float r0 = v.x - __half2float(h0), r1 = v.y - __half2float(h1);
    float r2 = v.z - __half2float(h2), r3 = v.w - __half2float(h3);
    float cl2 = r0 * r0 + r1 * r1 + r2 * r2 + r3 * r3;
    g_Bhat[(size_t)row * 64 + 2 * lane]     = pack_h2(h0, h1);
    g_Bhat[(size_t)row * 64 + 2 * lane + 1] = pack_h2(h2, h3);
    #pragma unroll
    for (int o = 16; o; o >>= 1) {
        c2  += __shfl_down_sync(0xFFFFFFFFu, c2, o);
        cl2 += __shfl_down_sync(0xFFFFFFFFu, cl2, o);
    }
    if (lane == 0) {
        g_c2[row] = c2;
        atomicMax(&g_clmax_bits[row >> 13], __float_as_int(cl2));
    }
}

// x2[n*BT+bt] = sum_d x^2
__global__ void x2_kernel(const float* __restrict__ x) {
    int bi = blockIdx.x;
    int n  = bi >> 8;
    int b  = (bi >> 5) & 7;
    int t0 = (bi & 31) * 32;
    int tt = threadIdx.x & 31;
    int g  = threadIdx.x >> 5;
    const float* xp = x + ((size_t)b * CCH + (size_t)n * DDIM) * TLEN + t0 + tt;
    float s = 0.f;
    #pragma unroll
    for (int j = 0; j < 16; ++j) {
        float v = xp[(size_t)(g * 16 + j) * TLEN];
        s += v * v;
    }
    __shared__ float sm[8][33];
    sm[g][tt] = s;
    __syncthreads();
    if (threadIdx.x < 32) {
        float tot = 0.f;
        #pragma unroll
        for (int j = 0; j < 8; ++j) tot += sm[j][threadIdx.x];
        g_x2[n * BT + b * TLEN + t0 + threadIdx.x] = tot;
    }
}

// split_x: Ahat[(n,bt)][128 u32] = f16x2 [xh(64) | xl(64)]
__global__ void split_x_kernel(const float* __restrict__ x) {
    __shared__ float xs[128 * 33];
    int bi = blockIdx.x;
    int n  = bi >> 8;
    int b  = (bi >> 5) & 7;
    int tc = bi & 31;
    int tid = threadIdx.x;
    int tt  = tid & 31;
    int dg  = tid >> 5;
    const float* xp = x + ((size_t)b * CCH + (size_t)n * DDIM) * TLEN + tc * 32 + tt;
    #pragma unroll
    for (int j = 0; j < 16; ++j) {
        int d = dg * 16 + j;
        xs[d * 33 + tt] = xp[(size_t)d * TLEN];
    }
    __syncthreads();
    #pragma unroll
    for (int it = 0; it < 16; ++it) {
        int lin = it * 256 + tid;
        int r   = lin >> 7;
        int w   = lin & 127;
        int bt  = b * TLEN + tc * 32 + r;
        float a, bb;
        if (w < 64) {
            a  = xs[(2 * w) * 33 + r];
            bb = xs[(2 * w + 1) * 33 + r];
            g_Ahat[(size_t)(n * BT + bt) * 128 + w] =
                pack_h2(__float2half_rn(a), __float2half_rn(bb));
        } else {
            int d0 = 2 * (w - 64);
            a  = xs[d0 * 33 + r];
            bb = xs[(d0 + 1) * 33 + r];
            __half ha = __float2half_rn(a), hb = __float2half_rn(bb);
            __half la = __float2half_rn(a - __half2float(ha));
            __half lb = __float2half_rn(bb - __half2float(hb));
            g_Ahat[(size_t)(n * BT + bt) * 128 + w] = pack_h2(la, lb);
        }
    }
}

// ---------------------------------------------------------------------------
// vq_mma: one CTA per (cb n, 128-query tile). 512 threads, 16 warps (8m x 2n).
// A = [xh|xl] 128q x 256 f16 in smem; B = ch tiles (64 cw x 128 f16)
// double-buffered via cp.async. Warp tile 16q x 32cw; effective K = 256,
// hi and lo A multiply the SAME B fragments.
// Epilogue: per-thread top-3 per query over its 1/8 of k-space; merge phase
// emits candidate set + rigorous per-thread-v3 certificate.
// ---------------------------------------------------------------------------
#define ASTRIDE 528
#define BSTRIDE 272
#define SM_A    0
#define SM_B0   67584
#define SM_B1   84992
#define SM_MV   102400
#define SM_MK   114688
#define SM_TOT  126976

__global__ void __launch_bounds__(512, 1)
vq_mma_kernel() {
    extern __shared__ char smraw[];
    const uint32_t sb = smem_u32(smraw);
    const int tid  = threadIdx.x;
    const int wid  = tid >> 5;
    const int lane = tid & 31;
    const int gq   = lane >> 2;
    const int tq   = lane & 3;
    const int mw   = wid >> 1;          // 0-7 (16q each)
    const int nw   = wid & 1;           // 0-1 (32cw each)
    const int n    = blockIdx.x >> 6;
    const int qbase = (blockIdx.x & 63) * 128;

    const char* bsrc = (const char*)g_Bhat + (size_t)n * KCB * 256;

    // ---- prologue: group0 = A tile + B tile0 ; group1 = B tile1 ----
    {
        const char* asrc = (const char*)g_Ahat + (size_t)(n * BT + qbase) * 512;
        #pragma unroll
        for (int it = 0; it < 8; ++it) {
            int c   = it * 512 + tid;
            int row = c >> 5, col = c & 31;
            cp_async16(sb + SM_A + row * ASTRIDE + col * 16,
                       asrc + (size_t)row * 512 + col * 16);
        }
        #pragma unroll
        for (int it = 0; it < 2; ++it) {
            int c   = it * 512 + tid;
            int row = c >> 4, col = c & 15;
            cp_async16(sb + SM_B0 + row * BSTRIDE + col * 16,
                       bsrc + (size_t)row * 256 + col * 16);
        }
        CP_COMMIT();
        #pragma unroll
        for (int it = 0; it < 2; ++it) {
            int c   = it * 512 + tid;
            int row = c >> 4, col = c & 15;
            cp_async16(sb + SM_B1 + row * BSTRIDE + col * 16,
                       bsrc + (size_t)(64 + row) * 256 + col * 16);
        }
        CP_COMMIT();
    }
    CP_WAIT1();
    __syncthreads();

    const uint32_t lmo = (uint32_t)(lane >> 4) * 16;
    const uint32_t aHi = sb + SM_A +
        (uint32_t)(mw * 16 + (lane & 15)) * ASTRIDE + lmo;
    const uint32_t bAddrP[2] = {
        sb + SM_B0 + (uint32_t)(nw * 32 + (lane & 15)) * BSTRIDE + lmo,
        sb + SM_B1 + (uint32_t)(nw * 32 + (lane & 15)) * BSTRIDE + lmo };

    float v1[2], v2[2], v3[2];
    int   k1[2], k2[2];
    #pragma unroll
    for (int i = 0; i < 2; ++i) {
        v1[i] = v2[i] = v3[i] = 3.4e38f;
        k1[i] = k2[i] = 0;
    }

    for (int iter = 0; iter < 128; ++iter) {
        float acc[4][4];
        #pragma unroll
        for (int nt = 0; nt < 4; ++nt)
            #pragma unroll
            for (int j = 0; j < 4; ++j) acc[nt][j] = 0.f;

        const uint32_t bA = bAddrP[iter & 1];
        #pragma unroll
        for (int ks = 0; ks < 8; ++ks) {
            uint32_t h0, h1, h2, h3, l0, l1, l2, l3;
            uint32_t b0x, b0y, b1x, b1y, b0z, b0w, b1z, b1w;
            ldsm4(h0, h1, h2, h3, aHi + ks * 32);
            ldsm4(l0, l1, l2, l3, aHi + 256 + ks * 32);
            ldsm4(b0x, b0y, b1x, b1y, bA + ks * 32);
            ldsm4(b0z, b0w, b1z, b1w, bA + 16 * BSTRIDE + ks * 32);
            mma_f16(acc[0], h0, h1, h2, h3, b0x, b1x);
            mma_f16(acc[1], h0, h1, h2, h3, b0y, b1y);
            mma_f16(acc[2], h0, h1, h2, h3, b0z, b1z);
            mma_f16(acc[3], h0, h1, h2, h3, b0w, b1w);
            mma_f16(acc[0], l0, l1, l2, l3, b0x, b1x);
            mma_f16(acc[1], l0, l1, l2, l3, b0y, b1y);
            mma_f16(acc[2], l0, l1, l2, l3, b0z, b1z);
            mma_f16(acc[3], l0, l1, l2, l3, b0w, b1w);
        }

        // ---- epilogue: s = c2[k] - 2*xc, per-row top-3 ----
        const int kbw = iter * 64 + nw * 32;
        #pragma unroll
        for (int nt = 0; nt < 4; ++nt) {
            const int kg = kbw + nt * 8 + tq * 2;
            const float2 c2p = __ldg(reinterpret_cast<const float2*>(
                g_c2 + n * KCB + kg));
            #pragma unroll
            for (int r = 0; r < 2; ++r) {
                float s0 = fmaf(acc[nt][r * 2 + 0], -2.0f, c2p.x);
                float s1 = fmaf(acc[nt][r * 2 + 1], -2.0f, c2p.y);
                if (s0 < v3[r]) {
                    if (s0 < v2[r]) {
                        v3[r] = v2[r];
                        if (s0 < v1[r]) { v2[r] = v1[r]; k2[r] = k1[r];
                                          v1[r] = s0;    k1[r] = kg; }
                        else            { v2[r] = s0;    k2[r] = kg; }
                    } else v3[r] = s0;
                }
                if (s1 < v3[r]) {
                    if (s1 < v2[r]) {
                        v3[r] = v2[r];
                        if (s1 < v1[r]) { v2[r] = v1[r]; k2[r] = k1[r];
                                          v1[r] = s1;    k1[r] = kg + 1; }
                        else            { v2[r] = s1;    k2[r] = kg + 1; }
                    } else v3[r] = s1;
                }
            }
        }

        __syncthreads();

        if (iter + 2 < 128) {
            const char* src = bsrc + (size_t)(iter + 2) * 64 * 256;
            uint32_t dstb = sb + ((iter & 1) ? SM_B1 : SM_B0);
            #pragma unroll
            for (int it = 0; it < 2; ++it) {
                int c   = it * 512 + tid;
                int row = c >> 4, col = c & 15;
                cp_async16(dstb + row * BSTRIDE + col * 16,
                           src + (size_t)row * 256 + col * 16);
            }
            CP_COMMIT();
            CP_WAIT1();
        } else {
            CP_WAIT0();
        }
        __syncthreads();
    }

    // ---- write per-thread top-3 lists (8 lists x 3 per query) ----
    float* MV = (float*)(smraw + SM_MV);
    int*   MK = (int*)(smraw + SM_MK);
    #pragma unroll
    for (int r = 0; r < 2; ++r) {
        const int ql = mw * 16 + r * 8 + gq;
        const int s0 = ql * 24 + (nw * 4 + tq) * 3;
        MV[s0 + 0] = v1[r]; MK[s0 + 0] = k1[r];
        MV[s0 + 1] = v2[r]; MK[s0 + 1] = k2[r];
        MV[s0 + 2] = v3[r]; MK[s0 + 2] = 0;
    }
    __syncthreads();

    // ---- merge + certificate + candidate emission (thread = query) ----
    if (tid < 128) {
        const int q = n * BT + qbase + tid;
        // global best (approx grid, lowest-k tie)
        float b1 = 3.4e38f;
        int   i1 = 1 << 30;
        #pragma unroll 4
        for (int j = 0; j < 24; ++j) {
            float v = MV[tid * 24 + j];
            int   k = MK[tid * 24 + j];
            if (v < b1 || (v == b1 && k < i1)) { b1 = v; i1 = k; }
        }
        // certificate: min over the 8 per-thread lists of their v3
        float minv3 = 3.4e38f;
        #pragma unroll
        for (int l = 0; l < 8; ++l)
            minv3 = fminf(minv3, MV[tid * 24 + l * 3 + 2]);
        // rigorous margin: 2*(e(k)+e(k1)), e <= ||x||*max||cl|| + slack
        float cl2m   = __int_as_float(g_clmax_bits[n]);
        float margin = 4.0f * sqrtf(g_x2[q]) * sqrtf(cl2m) + 1e-3f;

        int cnt;
        if (minv3 - b1 <= margin) {
            cnt = -1;   // a thread may have dropped an in-window value
        } else {
            cnt = 0;
            float thr = b1 + margin;
            #pragma unroll 4
            for (int j = 0; j < 24; ++j) {
                float v = MV[tid * 24 + j];
                if (v <= thr) {
                    if (cnt < 8) g_candk[q * 8 + cnt] = MK[tid * 24 + j];
                    ++cnt;
                }
            }
            if (cnt > 8) cnt = -1;
        }
        g_candn[q] = cnt;
    }
}

// ---------------------------------------------------------------------------
// exact JAX-order d2 (identical arithmetic to the passing rounds 1-3)
// ---------------------------------------------------------------------------
__device__ __forceinline__ float exact_d2(const float* __restrict__ x,
                                          const float* __restrict__ cb,
                                          int n, int b, int t, int bt, int k) {
    const float* xp = x + ((size_t)b * CCH + (size_t)n * DDIM) * TLEN + t;
    const float* cp = cb + ((size_t)n * KCB + (size_t)k) * DDIM;
    float xc = 0.f;
    #pragma unroll 8
    for (int d = 0; d < DDIM; ++d) xc = fmaf(xp[(size_t)d * TLEN], cp[d], xc);
    return __fadd_rn(__fsub_rn(g_x2[n * BT + bt], __fmul_rn(2.0f, xc)),
                     g_c2[n * KCB + k]);
}

// ---------------------------------------------------------------------------
// finalize: exact rescore of the (tiny) candidate set; flag fallbacks
// ---------------------------------------------------------------------------
__global__ void finalize_kernel(const float* __restrict__ x,
                                const float* __restrict__ cb,
                                float* __restrict__ out) {
    int q = blockIdx.x * 256 + threadIdx.x;
    int n = q >> 13, bt = q & 8191, b = bt >> 10, t = bt & 1023;
    int cnt = g_candn[q];
    if (cnt < 0) {
        int pos = atomicAdd(&g_nflag, 1);
        g_flagq[pos] = q;
        return;
    }
    int kf;
    if (cnt == 1) {
        kf = g_candk[q * 8];
    } else {
        float bd = 3.4e38f;
        kf = 1 << 30;
        for (int i = 0; i < cnt; ++i) {
            int   k = g_candk[q * 8 + i];
            float d = exact_d2(x, cb, n, b, t, bt, k);
            if (d < bd || (d == bd && k < kf)) { bd = d; kf = k; }
        }
    }
    g_idx[q] = kf;
    out[NQ + ((size_t)b * 2 + n) * TLEN + t] = (float)kf;
}

// ---------------------------------------------------------------------------
// fallback: exact full scan for flagged queries (expected ~0-20)
// ---------------------------------------------------------------------------
__global__ void fallback_kernel(const float* __restrict__ x,
                                const float* __restrict__ cb,
                                float* __restrict__ out) {
    __shared__ float sv[256];
    __shared__ int   sk[256];
    int nf = g_nflag;
    for (int i = blockIdx.x; i < nf; i += 128) {
        int q = g_flagq[i];
        int n = q >> 13, bt = q & 8191, b = bt >> 10, t = bt & 1023;
        float bv = 3.4e38f;
        int   bk = 1 << 30;
        for (int j = 0; j < 32; ++j) {
            int k = threadIdx.x + j * 256;
            float d2 = exact_d2(x, cb, n, b, t, bt, k);
            if (d2 < bv || (d2 == bv && k < bk)) { bv = d2; bk = k; }
        }
        sv[threadIdx.x] = bv;
        sk[threadIdx.x] = bk;
        __syncthreads();
        for (int o = 128; o; o >>= 1) {
            if (threadIdx.x < o) {
                float ov = sv[threadIdx.x + o];
                int   ok = sk[threadIdx.x + o];
                if (ov < sv[threadIdx.x] ||
                    (ov == sv[threadIdx.x] && ok < sk[threadIdx.x])) {
                    sv[threadIdx.x] = ov; sk[threadIdx.x] = ok;
                }
            }
            __syncthreads();
        }
        if (threadIdx.x == 0) {
            g_idx[q] = sk[0];
            out[NQ + ((size_t)b * 2 + n) * TLEN + t] = (float)sk[0];
        }
        __syncthreads();
    }
}

// ---------------------------------------------------------------------------
// gather quantized output + commit-loss SSE
// ---------------------------------------------------------------------------
__global__ void gather_kernel(const float* __restrict__ x,
                              const float* __restrict__ cb,
                              float* __restrict__ out) {
    int bi = blockIdx.x;
    int n  = bi >> 13;
    int bt = bi & 8191;
    int b  = bt >> 10;
    int t  = bt & 1023;
    int k  = g_idx[n * BT + bt];
    int i  = threadIdx.x;

    float q = cb[(size_t)n * KCB * DDIM + (size_t)k * DDIM + i];
    size_t oidx = ((size_t)b * CCH + (size_t)n * DDIM + i) * TLEN + t;
    out[oidx] = q;

    float d = x[oidx] - q;
    float s = d * d;
    #pragma unroll
    for (int o = 16; o; o >>= 1) s += __shfl_down_sync(0xFFFFFFFFu, s, o);
    __shared__ float sm4[4];
    if ((i & 31) == 0) sm4[i >> 5] = s;
    __syncthreads();
    if (i == 0)
        atomicAdd(&g_sse, (double)(sm4[0] + sm4[1] + sm4[2] + sm4[3]));
}

__global__ void fin_kernel(float* __restrict__ out) {
    out[NQ + NIDX] = (float)(0.25 * g_sse / (double)((long long)BT * DDIM));
}

// ---------------------------------------------------------------------------
extern "C" void kernel_launch(void* const* d_in, const int* in_sizes, int n_in,
                              void* d_out, int out_size) {
    const float* x  = (const float*)d_in[0];
    const float* cb = (const float*)d_in[1];
    float* out = (float*)d_out;

    cudaFuncSetAttribute(vq_mma_kernel,
                         cudaFuncAttributeMaxDynamicSharedMemorySize, SM_TOT);

    init_kernel<<<1, 32>>>();
    splitcb_kernel<<<2048, 256>>>(cb);
    x2_kernel<<<512, 256>>>(x);
    split_x_kernel<<<512, 256>>>(x);
    vq_mma_kernel<<<128, 512, SM_TOT>>>();
    finalize_kernel<<<64, 256>>>(x, cb, out);
    fallback_kernel<<<128, 256>>>(x, cb, out);
    gather_kernel<<<16384, 128>>>(x, cb, out);
    fin_kernel<<<1, 1>>>(out);
}